// round 7
// baseline (speedup 1.0000x reference)
#include <cuda_runtime.h>
#include <math.h>
#include <cstdint>

// Problem constants
#define DD     768
#define BINS   385
#define CPF    770          // valid floats per transform = 2*BINS
#define CPS    784          // section stride in F/M (16B aligned)
#define NCF    2432         // padded F/M width (19*128)
#define EPITCH 1024         // padded E width (8*128)
#define K2W    1536         // Wt hi|lo concatenated width
#define NTOK   16384
#define SEQ    4096
#define BATCH  4
#define KPAD   800          // padded OutF row length (25*32)

// Scratch (device globals; allocation-free per harness rules)
__device__ float g_E2[K2W * EPITCH];          // [Ehi ; Elo] rows, zero-padded cols
__device__ float g_Wt2[3 * DD * K2W];         // [Whi^T | Wlo^T] per projection
__device__ float g_Mp[3][DD * NCF];           // per-term partials (hi*hi, lo*hi, hi*lo)
__device__ float g_M[DD * NCF];               // final combined matrix (tf32-rounded)
__device__ float g_F[(size_t)NTOK * NCF];     // kf|vf|qf per token
__device__ float g_OutF[(size_t)NTOK * KPAD]; // mem*conj(qf), tf32-rounded
__device__ float g_G[KPAD * DD];              // inverse rDFT matrix, tf32-rounded

__device__ __forceinline__ float cvt_tf32(float x) {
    uint32_t u;
    asm("cvt.rna.tf32.f32 %0, %1;" : "=r"(u) : "f"(x));
    return __uint_as_float(u);
}
__device__ __forceinline__ float4 cvt4(float4 v) {
    float4 o;
    o.x = cvt_tf32(v.x); o.y = cvt_tf32(v.y);
    o.z = cvt_tf32(v.z); o.w = cvt_tf32(v.w);
    return o;
}

// ---------------------------------------------------------------------------
// Fill / prep kernels
// ---------------------------------------------------------------------------
__global__ void fill_E2() {
    int idx = blockIdx.x * blockDim.x + threadIdx.x;
    if (idx >= K2W * EPITCH) return;
    int r = idx / EPITCH, j = idx % EPITCH;
    float out = 0.f;
    if (j < CPF) {
        int e = r & (DD - 1) ? r % DD : 0;   // r % 768
        e = r % DD;
        int sec = r / DD;                    // 0 -> hi ; 1 -> lo
        int m = j >> 1;
        int rr = (e * m) % DD;
        float th = (float)rr * (float)(2.0 * M_PI / DD);
        float s, c;
        sincosf(th, &s, &c);
        float v = (j & 1) ? -s : c;
        float hi = cvt_tf32(v);
        out = (sec == 0) ? hi : cvt_tf32(v - hi);
    }
    g_E2[idx] = out;
}

__global__ void fill_G() {
    int idx = blockIdx.x * blockDim.x + threadIdx.x;
    if (idx >= KPAD * DD) return;
    int j = idx / DD, n = idx % DD;
    float v = 0.f;
    if (j < CPF) {
        int m = j >> 1;
        float w = (m == 0 || m == BINS - 1) ? 1.f : 2.f;
        int r = (m * n) % DD;
        float th = (float)r * (float)(2.0 * M_PI / DD);
        float s, c;
        sincosf(th, &s, &c);
        v = cvt_tf32(((j & 1) ? -s : c) * (w / (float)DD));
    }
    g_G[idx] = v;
}

// Transpose + hi/lo split: g_Wt2[p][d][e] = hi, g_Wt2[p][d][768+e] = lo
__global__ void transpose_w(const float* __restrict__ Wk,
                            const float* __restrict__ Wv,
                            const float* __restrict__ Wq) {
    __shared__ float t[32][33];
    const float* W = (blockIdx.z == 0) ? Wk : ((blockIdx.z == 1) ? Wv : Wq);
    float* T = g_Wt2 + (size_t)blockIdx.z * DD * K2W;
    int bx = blockIdx.x * 32, by = blockIdx.y * 32;
#pragma unroll
    for (int i = 0; i < 4; i++) {
        int e = by + threadIdx.y + i * 8;
        t[threadIdx.y + i * 8][threadIdx.x] = W[(size_t)e * DD + bx + threadIdx.x];
    }
    __syncthreads();
#pragma unroll
    for (int i = 0; i < 4; i++) {
        int d = bx + threadIdx.y + i * 8;
        float v = t[threadIdx.x][threadIdx.y + i * 8];
        float hi = cvt_tf32(v);
        float lo = cvt_tf32(v - hi);
        size_t base = (size_t)d * K2W + by + threadIdx.x;
        T[base] = hi;
        T[base + DD] = lo;
    }
}

// Combine precompute partials: M = round_tf32(hi*hi + lo*hi + hi*lo), pads -> 0
__global__ void reduce_M() {
    int i = blockIdx.x * blockDim.x + threadIdx.x;
    if (i >= DD * NCF) return;
    int c = i % NCF;
    float v = 0.f;
    if (c < 3 * CPS && (c % CPS) < CPF)
        v = cvt_tf32(g_Mp[0][i] + g_Mp[1][i] + g_Mp[2][i]);
    g_M[i] = v;
}

// ---------------------------------------------------------------------------
// TF32 tensor GEMM (R2-proven structure): C = A[M,K] * B[K,N], row-major,
// 128x128 tile, BK=32, 2-stage smem + register prefetch, cvt at STS.
// 256 threads (8 warps 2x4, warp tile 64x32). 2 CTAs/SM by smem.
// MODE 0: plain store. MODE 1: C = X + gain*acc.
// MODE 2 (precompute): z = proj*3 + term; A/B offset per term, store raw
//   partial into g_Mp[term] at col offset proj*CPS, only col < nvalid.
// ---------------------------------------------------------------------------
#define GBM 128
#define GBN 128
#define GBK 32
#define APD 36
#define BPD 136
#define A_ST (GBM * APD)     // 4608 floats per stage
#define B_ST (GBK * BPD)     // 4352 floats per stage
#define SMEMB ((2 * A_ST + 2 * B_ST) * 4)   // 71680 B

__device__ __forceinline__ void ldsm4(uint32_t* r, uint32_t addr) {
    asm volatile("ldmatrix.sync.aligned.m8n8.x4.shared.b16 {%0,%1,%2,%3}, [%4];\n"
        : "=r"(r[0]), "=r"(r[1]), "=r"(r[2]), "=r"(r[3]) : "r"(addr));
}
__device__ __forceinline__ void mma_tf32(float* d, const uint32_t* a, const uint32_t* b) {
    asm volatile(
        "mma.sync.aligned.m16n8k8.row.col.f32.tf32.tf32.f32 "
        "{%0,%1,%2,%3}, {%4,%5,%6,%7}, {%8,%9}, {%0,%1,%2,%3};\n"
        : "+f"(d[0]), "+f"(d[1]), "+f"(d[2]), "+f"(d[3])
        : "r"(a[0]), "r"(a[1]), "r"(a[2]), "r"(a[3]), "r"(b[0]), "r"(b[1]));
}

template <int MODE>
__global__ __launch_bounds__(256) void gemm_tc(
    int K,
    const float* __restrict__ A, int lda,
    const float* __restrict__ B, int ldb,
    float* __restrict__ C, int ldc,
    const float* __restrict__ X, const float* __restrict__ gainp,
    int nvalid)
{
    extern __shared__ float sm[];
    float* smA = sm;              // [2][GBM][APD]
    float* smB = sm + 2 * A_ST;   // [2][GBK][BPD]

    const int tid  = threadIdx.x;
    const int lane = tid & 31;
    const int wid  = tid >> 5;
    const int wm   = (wid >> 2) * 64;
    const int wn   = (wid & 3) * 32;
    const int bm0  = blockIdx.y * GBM;
    const int bn0  = blockIdx.x * GBN;

    const float* Ab = A;
    const float* Bb = B;
    float* Cb = C;
    int coff = 0;
    if (MODE == 2) {
        int proj = blockIdx.z / 3, term = blockIdx.z % 3;
        // term 0: Whi * Ehi ; term 1: Wlo * Ehi ; term 2: Whi * Elo
        Ab = A + (size_t)proj * DD * K2W + ((term == 1) ? DD : 0);
        Bb = B + ((term == 2) ? (size_t)DD * EPITCH : 0);
        Cb = C + (size_t)term * (DD * NCF);
        coff = proj * CPS;
    }

    // gmem staging mapping (R2)
    const int arow = tid >> 3;          // 0..31
    const int acol = (tid & 7) * 4;     // 0..28
    const int brow = tid >> 5;          // 0..7
    const int bcol = (tid & 31) * 4;    // 0..124

    const float* Aptr = Ab + (size_t)(bm0 + arow) * lda + acol;
    const float* Bptr = Bb + (size_t)brow * ldb + bn0 + bcol;

    // A fragment ldmatrix addressing
    const int rin = lane & 7;
    const int sel = lane >> 3;
    const int aoff = (wm + (sel & 1) * 8 + rin) * APD + (sel >> 1) * 4;
    const uint32_t smA_u = (uint32_t)__cvta_generic_to_shared(smA);
    // B fragment scalar-lds addressing
    const int bkf = lane & 3;
    const int bnf = wn + (lane >> 2);

    float4 rA[4], rB[4];
    // prologue: tile 0
#pragma unroll
    for (int r = 0; r < 4; r++)
        rA[r] = *reinterpret_cast<const float4*>(Aptr + (size_t)(r * 32) * lda);
#pragma unroll
    for (int r = 0; r < 4; r++)
        rB[r] = *reinterpret_cast<const float4*>(Bptr + (size_t)(r * 8) * ldb);
#pragma unroll
    for (int r = 0; r < 4; r++)
        *reinterpret_cast<float4*>(&smA[(arow + r * 32) * APD + acol]) = cvt4(rA[r]);
#pragma unroll
    for (int r = 0; r < 4; r++)
        *reinterpret_cast<float4*>(&smB[(brow + r * 8) * BPD + bcol]) = cvt4(rB[r]);
    __syncthreads();

    float acc[4][4][4];
#pragma unroll
    for (int mf = 0; mf < 4; mf++)
#pragma unroll
        for (int nf = 0; nf < 4; nf++)
#pragma unroll
            for (int q = 0; q < 4; q++) acc[mf][nf][q] = 0.f;

    const int KT = K / GBK;
    int st = 0;
    for (int kt = 0; kt < KT; kt++) {
        if (kt + 1 < KT) {
            size_t k0n = (size_t)(kt + 1) * GBK;
#pragma unroll
            for (int r = 0; r < 4; r++)
                rA[r] = *reinterpret_cast<const float4*>(Aptr + (size_t)(r * 32) * lda + k0n);
#pragma unroll
            for (int r = 0; r < 4; r++)
                rB[r] = *reinterpret_cast<const float4*>(Bptr + (k0n + r * 8) * ldb);
        }
        // compute current stage
        {
            const uint32_t aBase = smA_u + (uint32_t)(st * A_ST) * 4;
            const float* pb = smB + st * B_ST;
#pragma unroll
            for (int ks = 0; ks < 4; ks++) {
                uint32_t a[4][4];
#pragma unroll
                for (int mf = 0; mf < 4; mf++)
                    ldsm4(a[mf], aBase + (uint32_t)(aoff + mf * 16 * APD + ks * 8) * 4);
                uint32_t b[4][2];
#pragma unroll
                for (int nf = 0; nf < 4; nf++) {
                    b[nf][0] = __float_as_uint(pb[(ks * 8 + bkf) * BPD + bnf + nf * 8]);
                    b[nf][1] = __float_as_uint(pb[(ks * 8 + bkf + 4) * BPD + bnf + nf * 8]);
                }
#pragma unroll
                for (int mf = 0; mf < 4; mf++)
#pragma unroll
                    for (int nf = 0; nf < 4; nf++)
                        mma_tf32(acc[mf][nf], a[mf], b[nf]);
            }
        }
        if (kt + 1 < KT) {
            int ns = st ^ 1;
            float* dA = smA + ns * A_ST;
            float* dB = smB + ns * B_ST;
#pragma unroll
            for (int r = 0; r < 4; r++)
                *reinterpret_cast<float4*>(&dA[(arow + r * 32) * APD + acol]) = cvt4(rA[r]);
#pragma unroll
            for (int r = 0; r < 4; r++)
                *reinterpret_cast<float4*>(&dB[(brow + r * 8) * BPD + bcol]) = cvt4(rB[r]);
        }
        __syncthreads();
        st ^= 1;
    }

    // epilogue
    float g = (MODE == 1) ? gainp[0] : 0.f;
#pragma unroll
    for (int mf = 0; mf < 4; mf++) {
        int row = bm0 + wm + mf * 16 + (lane >> 2);
#pragma unroll
        for (int nf = 0; nf < 4; nf++) {
            int col = bn0 + wn + nf * 8 + (lane & 3) * 2;
            size_t i0 = (size_t)row * ldc + coff + col;
            size_t i1 = i0 + (size_t)8 * ldc;
            if (MODE == 2) {
                if (col < nvalid) {
                    *reinterpret_cast<float2*>(Cb + i0) =
                        make_float2(acc[mf][nf][0], acc[mf][nf][1]);
                    *reinterpret_cast<float2*>(Cb + i1) =
                        make_float2(acc[mf][nf][2], acc[mf][nf][3]);
                }
            } else if (MODE == 1) {
                float2 x0 = *reinterpret_cast<const float2*>(X + i0);
                float2 x1 = *reinterpret_cast<const float2*>(X + i1);
                *reinterpret_cast<float2*>(Cb + i0) =
                    make_float2(x0.x + g * acc[mf][nf][0], x0.y + g * acc[mf][nf][1]);
                *reinterpret_cast<float2*>(Cb + i1) =
                    make_float2(x1.x + g * acc[mf][nf][2], x1.y + g * acc[mf][nf][3]);
            } else {
                *reinterpret_cast<float2*>(Cb + i0) =
                    make_float2(acc[mf][nf][0], acc[mf][nf][1]);
                *reinterpret_cast<float2*>(Cb + i1) =
                    make_float2(acc[mf][nf][2], acc[mf][nf][3]);
            }
        }
    }
}

// ---------------------------------------------------------------------------
// Causal complex cumsum of kf*vf per (batch, bin), times conj(qf).
// 2 bins/thread via float4; inactive threads zero the OutF pad columns.
// grid (BATCH, 25), block (8, 32).
// ---------------------------------------------------------------------------
__global__ void scan_kernel() {
    int b = blockIdx.x, mg = blockIdx.y;
    int j = threadIdx.x, l = threadIdx.y;
    int m0 = mg * 16 + 2 * j;
    bool a0 = m0 < BINS, a1 = (m0 + 1) < BINS;
    const int CH = SEQ / 32;   // 128
    int sbase = b * SEQ + l * CH;
    int km = 2 * m0;

    float s0r = 0.f, s0i = 0.f, s1r = 0.f, s1i = 0.f;
    const float* bp = g_F + (size_t)sbase * NCF + km;
    if (a1) {
#pragma unroll 4
        for (int i = 0; i < CH; i++) {
            const float* row = bp + (size_t)i * NCF;
            float4 k4 = *reinterpret_cast<const float4*>(row);
            float4 v4 = *reinterpret_cast<const float4*>(row + CPS);
            s0r += k4.x * v4.x - k4.y * v4.y;
            s0i += k4.x * v4.y + k4.y * v4.x;
            s1r += k4.z * v4.z - k4.w * v4.w;
            s1i += k4.z * v4.w + k4.w * v4.z;
        }
    } else if (a0) {
        for (int i = 0; i < CH; i++) {
            const float* row = bp + (size_t)i * NCF;
            float2 k2 = *reinterpret_cast<const float2*>(row);
            float2 v2 = *reinterpret_cast<const float2*>(row + CPS);
            s0r += k2.x * v2.x - k2.y * v2.y;
            s0i += k2.x * v2.y + k2.y * v2.x;
        }
    }
    __shared__ float p0r[8][33], p0i[8][33], p1r[8][33], p1i[8][33];
    p0r[j][l] = s0r; p0i[j][l] = s0i; p1r[j][l] = s1r; p1i[j][l] = s1i;
    __syncthreads();
    if (l == 0) {
        float a = 0.f, c = 0.f, d = 0.f, e = 0.f;
        for (int q = 0; q < 32; q++) {
            float t0 = p0r[j][q], t1 = p0i[j][q], t2 = p1r[j][q], t3 = p1i[j][q];
            p0r[j][q] = a; p0i[j][q] = c; p1r[j][q] = d; p1i[j][q] = e;
            a += t0; c += t1; d += t2; e += t3;
        }
    }
    __syncthreads();
    float m0r = p0r[j][l], m0i = p0i[j][l], m1r = p1r[j][l], m1i = p1i[j][l];
    float* op = g_OutF + (size_t)sbase * KPAD + km;
    if (a1) {
#pragma unroll 2
        for (int i = 0; i < CH; i++) {
            const float* row = bp + (size_t)i * NCF;
            float4 k4 = *reinterpret_cast<const float4*>(row);
            float4 v4 = *reinterpret_cast<const float4*>(row + CPS);
            float4 q4 = *reinterpret_cast<const float4*>(row + 2 * CPS);
            m0r += k4.x * v4.x - k4.y * v4.y;
            m0i += k4.x * v4.y + k4.y * v4.x;
            m1r += k4.z * v4.z - k4.w * v4.w;
            m1i += k4.z * v4.w + k4.w * v4.z;
            float4 o;
            o.x = cvt_tf32(m0r * q4.x + m0i * q4.y);
            o.y = cvt_tf32(m0i * q4.x - m0r * q4.y);
            o.z = cvt_tf32(m1r * q4.z + m1i * q4.w);
            o.w = cvt_tf32(m1i * q4.z - m1r * q4.w);
            *reinterpret_cast<float4*>(op + (size_t)i * KPAD) = o;
        }
    } else if (a0) {
        // bin m0 valid, m0+1 is pad: emit {valid, valid, 0, 0}
        for (int i = 0; i < CH; i++) {
            const float* row = bp + (size_t)i * NCF;
            float2 k2 = *reinterpret_cast<const float2*>(row);
            float2 v2 = *reinterpret_cast<const float2*>(row + CPS);
            float2 q2 = *reinterpret_cast<const float2*>(row + 2 * CPS);
            m0r += k2.x * v2.x - k2.y * v2.y;
            m0i += k2.x * v2.y + k2.y * v2.x;
            float4 o;
            o.x = cvt_tf32(m0r * q2.x + m0i * q2.y);
            o.y = cvt_tf32(m0i * q2.x - m0r * q2.y);
            o.z = 0.f; o.w = 0.f;
            *reinterpret_cast<float4*>(op + (size_t)i * KPAD) = o;
        }
    } else {
        // both bins are pad: zero-fill (cols up to KPAD)
        for (int i = 0; i < CH; i++)
            *reinterpret_cast<float4*>(op + (size_t)i * KPAD) =
                make_float4(0.f, 0.f, 0.f, 0.f);
    }
}

// ---------------------------------------------------------------------------
// Launch
// ---------------------------------------------------------------------------
extern "C" void kernel_launch(void* const* d_in, const int* in_sizes, int n_in,
                              void* d_out, int out_size) {
    const float* x    = (const float*)d_in[0];
    const float* Wk   = (const float*)d_in[1];
    const float* Wv   = (const float*)d_in[2];
    const float* Wq   = (const float*)d_in[3];
    const float* gain = (const float*)d_in[4];
    float* out = (float*)d_out;

    float *pE2, *pWt2, *pMp, *pM, *pF, *pO, *pG;
    cudaGetSymbolAddress((void**)&pE2,  g_E2);
    cudaGetSymbolAddress((void**)&pWt2, g_Wt2);
    cudaGetSymbolAddress((void**)&pMp,  g_Mp);
    cudaGetSymbolAddress((void**)&pM,   g_M);
    cudaGetSymbolAddress((void**)&pF,   g_F);
    cudaGetSymbolAddress((void**)&pO,   g_OutF);
    cudaGetSymbolAddress((void**)&pG,   g_G);

    cudaFuncSetAttribute(gemm_tc<0>, cudaFuncAttributeMaxDynamicSharedMemorySize, SMEMB);
    cudaFuncSetAttribute(gemm_tc<1>, cudaFuncAttributeMaxDynamicSharedMemorySize, SMEMB);
    cudaFuncSetAttribute(gemm_tc<2>, cudaFuncAttributeMaxDynamicSharedMemorySize, SMEMB);

    transpose_w<<<dim3(DD / 32, DD / 32, 3), dim3(32, 8)>>>(Wk, Wv, Wq);
    fill_E2<<<(K2W * EPITCH + 255) / 256, 256>>>();
    fill_G<<<(KPAD * DD + 255) / 256, 256>>>();

    // Precompute partials: z = proj*3 + term over (Whi|Wlo) x (Ehi|Elo)
    gemm_tc<2><<<dim3(EPITCH / GBN, DD / GBM, 9), 256, SMEMB>>>(
        DD, pWt2, K2W, pE2, EPITCH, pMp, NCF, nullptr, nullptr, CPF);
    reduce_M<<<(DD * NCF + 255) / 256, 256>>>();

    // Forward: F = x @ M (cvt of A happens at STS inside the GEMM)
    gemm_tc<0><<<dim3(NCF / GBN, NTOK / GBM), 256, SMEMB>>>(
        DD, x, DD, pM, NCF, pF, NCF, nullptr, nullptr, 0);

    // Causal binding scan (also zero-fills OutF pad columns)
    scan_kernel<<<dim3(BATCH, 25), dim3(8, 32)>>>();

    // Inverse: out = x + gain * (OutF @ G)
    gemm_tc<1><<<dim3(DD / GBN, NTOK / GBM), 256, SMEMB>>>(
        KPAD, pO, KPAD, pG, DD, out, DD, x, gain, 0);
}

// round 8
// speedup vs baseline: 1.2154x; 1.2154x over previous
#include <cuda_runtime.h>
#include <math.h>
#include <cstdint>

// Problem constants
#define DD     768
#define BINS   385
#define CPF    770          // floats per transform = 2*BINS
#define NVALID 2310         // 3*CPF valid F columns
#define NCF    2432         // padded F width (19*128)
#define NTOK   16384        // B*S
#define SEQ    4096
#define BATCH  4
#define KPAD   800          // padded outF row length (25*32)
#define K3     2304         // 3*DD (3xTF32 precompute K)
#define EP3    896          // E3 padded width (7*128)

// Scratch (device globals; allocation-free per harness rules)
__device__ float g_Wt3[3 * DD * K3];         // [W | Wlo | W] transposed, per projection
__device__ float g_E3[K3 * EP3];             // [E ; E ; Elo], zero-padded cols
__device__ float g_M[DD * NCF];              // combined Wk^T*E | Wv^T*E | Wq^T*E (CPF offsets)
__device__ float g_F[(size_t)NTOK * NCF];    // kf|vf|qf per token
__device__ float g_OutF[(size_t)NTOK * KPAD];// mem * conj(qf), K-padded
__device__ float g_G[KPAD * DD];             // inverse rDFT matrix [j][n]

__device__ __forceinline__ float cvt_tf32(float x) {
    uint32_t u;
    asm("cvt.rna.tf32.f32 %0, %1;" : "=r"(u) : "f"(x));
    return __uint_as_float(u);
}
__device__ __forceinline__ float4 cvt4(float4 v) {
    float4 o;
    o.x = cvt_tf32(v.x); o.y = cvt_tf32(v.y);
    o.z = cvt_tf32(v.z); o.w = cvt_tf32(v.w);
    return o;
}

// ---------------------------------------------------------------------------
// Fill kernels
// ---------------------------------------------------------------------------
__global__ void fill_E3() {
    int idx = blockIdx.x * blockDim.x + threadIdx.x;
    if (idx >= K3 * EP3) return;
    int r = idx / EP3, j = idx % EP3;
    float out = 0.f;
    if (j < CPF) {
        int e = r % DD;
        int sec = r / DD;            // 0,1 -> E (hi after STS-cvt) ; 2 -> Elo
        int m = j >> 1;
        int rr = (e * m) % DD;
        float th = (float)rr * (float)(2.0 * M_PI / DD);
        float s, c;
        sincosf(th, &s, &c);
        float v = (j & 1) ? -s : c;
        out = (sec < 2) ? v : (v - cvt_tf32(v));
    }
    g_E3[idx] = out;
}

__global__ void fill_G() {
    int idx = blockIdx.x * blockDim.x + threadIdx.x;
    if (idx >= KPAD * DD) return;
    int j = idx / DD, n = idx % DD;
    float v = 0.f;
    if (j < CPF) {
        int m = j >> 1;
        float w = (m == 0 || m == BINS - 1) ? 1.f : 2.f;
        int r = (m * n) % DD;
        float th = (float)r * (float)(2.0 * M_PI / DD);
        float s, c;
        sincosf(th, &s, &c);
        v = ((j & 1) ? -s : c) * (w / (float)DD);
    }
    g_G[idx] = v;
}

__global__ void zero_pad_outf() {
    int idx = blockIdx.x * blockDim.x + threadIdx.x;
    const int PADC = KPAD - CPF; // 30
    if (idx >= NTOK * PADC) return;
    int t = idx / PADC, c = CPF + idx % PADC;
    g_OutF[(size_t)t * KPAD + c] = 0.f;
}

// Transpose + hi/lo split: [W | Wlo | W] rows (d-major, K3 stride)
__global__ void transpose_w(const float* __restrict__ Wk,
                            const float* __restrict__ Wv,
                            const float* __restrict__ Wq) {
    __shared__ float t[32][33];
    const float* W = (blockIdx.z == 0) ? Wk : ((blockIdx.z == 1) ? Wv : Wq);
    float* T = g_Wt3 + (size_t)blockIdx.z * DD * K3;
    int bx = blockIdx.x * 32, by = blockIdx.y * 32;
#pragma unroll
    for (int i = 0; i < 4; i++) {
        int e = by + threadIdx.y + i * 8;
        t[threadIdx.y + i * 8][threadIdx.x] = W[(size_t)e * DD + bx + threadIdx.x];
    }
    __syncthreads();
#pragma unroll
    for (int i = 0; i < 4; i++) {
        int d = bx + threadIdx.y + i * 8;
        float v = t[threadIdx.x][threadIdx.y + i * 8];
        size_t base = (size_t)d * K3 + by + threadIdx.x;
        T[base] = v;                        // -> hi at STS-cvt
        T[base + DD] = v - cvt_tf32(v);     // lo
        T[base + 2 * DD] = v;               // -> hi at STS-cvt
    }
}

// ---------------------------------------------------------------------------
// Shared GEMM building blocks
// ---------------------------------------------------------------------------
#define GBM 128
#define GBN 128
#define GBK 32
#define APAD 36                 // smem A row stride (floats) -> conflict-free ldmatrix
#define BPAD 136                // smem B row stride (floats) -> conflict-free lds
#define A_ST (GBM * APAD)       // 4608 floats per stage
#define B_ST (GBK * BPAD)       // 4352 floats per stage
#define GSMEM_BYTES ((2 * A_ST + 2 * B_ST) * 4)   // 71680 B

__device__ __forceinline__ void ldsm4(uint32_t* r, uint32_t addr) {
    asm volatile("ldmatrix.sync.aligned.m8n8.x4.shared.b16 {%0,%1,%2,%3}, [%4];\n"
        : "=r"(r[0]), "=r"(r[1]), "=r"(r[2]), "=r"(r[3]) : "r"(addr));
}
__device__ __forceinline__ void mma_tf32(float* d, const uint32_t* a, const uint32_t* b) {
    asm volatile(
        "mma.sync.aligned.m16n8k8.row.col.f32.tf32.tf32.f32 "
        "{%0,%1,%2,%3}, {%4,%5,%6,%7}, {%8,%9}, {%0,%1,%2,%3};\n"
        : "+f"(d[0]), "+f"(d[1]), "+f"(d[2]), "+f"(d[3])
        : "r"(a[0]), "r"(a[1]), "r"(a[2]), "r"(a[3]), "r"(b[0]), "r"(b[1]));
}

// ---------------------------------------------------------------------------
// Main TF32 GEMM (R2-measured structure): C[M,N] = A[M,K]*B[K,N], row-major.
// 2-stage smem + register prefetch, cvt at STS. N,M mult of 128, K mult of 32.
// Optional epilogue C = X + gain*acc. gridDim.z selects A0/A1/A2 with column
// offset z*zcolstride in C. 2 CTAs/SM via launch bounds.
// ---------------------------------------------------------------------------
__global__ __launch_bounds__(256, 2) void gemm_tf32(
    int M, int N, int K,
    const float* __restrict__ A0, const float* __restrict__ A1,
    const float* __restrict__ A2, int lda,
    const float* __restrict__ B, int ldb,
    float* __restrict__ C, int ldc, int zcolstride,
    int epi, const float* __restrict__ X, const float* __restrict__ gainp)
{
    extern __shared__ float sm[];
    float* smA = sm;              // [2][GBM][APAD]
    float* smB = sm + 2 * A_ST;   // [2][GBK][BPAD]

    const float* A = (blockIdx.z == 0) ? A0 : ((blockIdx.z == 1) ? A1 : A2);
    const int coff = blockIdx.z * zcolstride;

    const int tid  = threadIdx.x;
    const int lane = tid & 31;
    const int wid  = tid >> 5;
    const int wm   = (wid >> 2) * 64;
    const int wn   = (wid & 3) * 32;
    const int bm0  = blockIdx.y * GBM;
    const int bn0  = blockIdx.x * GBN;

    const int arow = tid >> 3;          // 0..31
    const int acol = (tid & 7) * 4;     // 0..28
    const int brow = tid >> 5;          // 0..7
    const int bcol = (tid & 31) * 4;    // 0..124

    const float* Aptr = A + (size_t)(bm0 + arow) * lda + acol;
    const float* Bptr = B + (size_t)brow * ldb + bn0 + bcol;

    const int rin = lane & 7;
    const int sel = lane >> 3;
    const int aoff = (wm + (sel & 1) * 8 + rin) * APAD + (sel >> 1) * 4;
    const uint32_t smA_u = (uint32_t)__cvta_generic_to_shared(smA);
    const int bk_f = lane & 3;
    const int bn_f = wn + (lane >> 2);

    float4 rA[4], rB[4];
#pragma unroll
    for (int r = 0; r < 4; r++)
        rA[r] = *reinterpret_cast<const float4*>(Aptr + (size_t)(r * 32) * lda);
#pragma unroll
    for (int r = 0; r < 4; r++)
        rB[r] = *reinterpret_cast<const float4*>(Bptr + (size_t)(r * 8) * ldb);
#pragma unroll
    for (int r = 0; r < 4; r++)
        *reinterpret_cast<float4*>(&smA[(arow + r * 32) * APAD + acol]) = cvt4(rA[r]);
#pragma unroll
    for (int r = 0; r < 4; r++)
        *reinterpret_cast<float4*>(&smB[(brow + r * 8) * BPAD + bcol]) = cvt4(rB[r]);
    __syncthreads();

    float acc[4][4][4];
#pragma unroll
    for (int mf = 0; mf < 4; mf++)
#pragma unroll
        for (int nf = 0; nf < 4; nf++)
#pragma unroll
            for (int q = 0; q < 4; q++) acc[mf][nf][q] = 0.f;

    const int KT = K / GBK;
    int st = 0;
    for (int kt = 0; kt < KT; kt++) {
        if (kt + 1 < KT) {
            size_t k0n = (size_t)(kt + 1) * GBK;
#pragma unroll
            for (int r = 0; r < 4; r++)
                rA[r] = *reinterpret_cast<const float4*>(Aptr + (size_t)(r * 32) * lda + k0n);
#pragma unroll
            for (int r = 0; r < 4; r++)
                rB[r] = *reinterpret_cast<const float4*>(Bptr + (k0n + r * 8) * ldb);
        }
        {
            const uint32_t aBase = smA_u + (uint32_t)(st * A_ST) * 4;
            const float* pb = smB + st * B_ST;
#pragma unroll
            for (int ks = 0; ks < 4; ks++) {
                uint32_t a[4][4];
#pragma unroll
                for (int mf = 0; mf < 4; mf++)
                    ldsm4(a[mf], aBase + (uint32_t)(aoff + mf * 16 * APAD + ks * 8) * 4);
                uint32_t b[4][2];
#pragma unroll
                for (int nf = 0; nf < 4; nf++) {
                    b[nf][0] = __float_as_uint(pb[(ks * 8 + bk_f) * BPAD + bn_f + nf * 8]);
                    b[nf][1] = __float_as_uint(pb[(ks * 8 + bk_f + 4) * BPAD + bn_f + nf * 8]);
                }
#pragma unroll
                for (int mf = 0; mf < 4; mf++)
#pragma unroll
                    for (int nf = 0; nf < 4; nf++)
                        mma_tf32(acc[mf][nf], a[mf], b[nf]);
            }
        }
        if (kt + 1 < KT) {
            int ns = st ^ 1;
            float* dA = smA + ns * A_ST;
            float* dB = smB + ns * B_ST;
#pragma unroll
            for (int r = 0; r < 4; r++)
                *reinterpret_cast<float4*>(&dA[(arow + r * 32) * APAD + acol]) = cvt4(rA[r]);
#pragma unroll
            for (int r = 0; r < 4; r++)
                *reinterpret_cast<float4*>(&dB[(brow + r * 8) * BPAD + bcol]) = cvt4(rB[r]);
        }
        __syncthreads();
        st ^= 1;
    }

    float g = epi ? gainp[0] : 0.f;
#pragma unroll
    for (int mf = 0; mf < 4; mf++) {
        int row = bm0 + wm + mf * 16 + (lane >> 2);
#pragma unroll
        for (int nf = 0; nf < 4; nf++) {
            int col = bn0 + wn + nf * 8 + (lane & 3) * 2;
            size_t i0 = (size_t)row * ldc + coff + col;
            size_t i1 = i0 + (size_t)8 * ldc;
            float2 v0 = make_float2(acc[mf][nf][0], acc[mf][nf][1]);
            float2 v1 = make_float2(acc[mf][nf][2], acc[mf][nf][3]);
            if (epi) {
                float2 x0 = *reinterpret_cast<const float2*>(X + i0);
                float2 x1 = *reinterpret_cast<const float2*>(X + i1);
                v0.x = x0.x + g * v0.x; v0.y = x0.y + g * v0.y;
                v1.x = x1.x + g * v1.x; v1.y = x1.y + g * v1.y;
            }
            *reinterpret_cast<float2*>(C + i0) = v0;
            *reinterpret_cast<float2*>(C + i1) = v1;
        }
    }
}

// ---------------------------------------------------------------------------
// Precompute GEMM (isolated clone): M_p = [W|Wlo|W]_p @ [E;E;Elo]  (3xTF32).
// z = projection. Guarded fp32 store into g_M at col offset z*CPF, col<CPF.
// grid (7, 6, 3). Cannot perturb the main GEMM's codegen.
// ---------------------------------------------------------------------------
__global__ __launch_bounds__(256, 2) void gemm_pre() {
    extern __shared__ float sm[];
    float* smA = sm;
    float* smB = sm + 2 * A_ST;

    const float* A = g_Wt3 + (size_t)blockIdx.z * DD * K3;
    const int coff = blockIdx.z * CPF;

    const int tid  = threadIdx.x;
    const int lane = tid & 31;
    const int wid  = tid >> 5;
    const int wm   = (wid >> 2) * 64;
    const int wn   = (wid & 3) * 32;
    const int bm0  = blockIdx.y * GBM;
    const int bn0  = blockIdx.x * GBN;

    const int arow = tid >> 3;
    const int acol = (tid & 7) * 4;
    const int brow = tid >> 5;
    const int bcol = (tid & 31) * 4;

    const float* Aptr = A + (size_t)(bm0 + arow) * K3 + acol;
    const float* Bptr = g_E3 + (size_t)brow * EP3 + bn0 + bcol;

    const int rin = lane & 7;
    const int sel = lane >> 3;
    const int aoff = (wm + (sel & 1) * 8 + rin) * APAD + (sel >> 1) * 4;
    const uint32_t smA_u = (uint32_t)__cvta_generic_to_shared(smA);
    const int bk_f = lane & 3;
    const int bn_f = wn + (lane >> 2);

    float4 rA[4], rB[4];
#pragma unroll
    for (int r = 0; r < 4; r++)
        rA[r] = *reinterpret_cast<const float4*>(Aptr + (size_t)(r * 32) * K3);
#pragma unroll
    for (int r = 0; r < 4; r++)
        rB[r] = *reinterpret_cast<const float4*>(Bptr + (size_t)(r * 8) * EP3);
#pragma unroll
    for (int r = 0; r < 4; r++)
        *reinterpret_cast<float4*>(&smA[(arow + r * 32) * APAD + acol]) = cvt4(rA[r]);
#pragma unroll
    for (int r = 0; r < 4; r++)
        *reinterpret_cast<float4*>(&smB[(brow + r * 8) * BPAD + bcol]) = cvt4(rB[r]);
    __syncthreads();

    float acc[4][4][4];
#pragma unroll
    for (int mf = 0; mf < 4; mf++)
#pragma unroll
        for (int nf = 0; nf < 4; nf++)
#pragma unroll
            for (int q = 0; q < 4; q++) acc[mf][nf][q] = 0.f;

    const int KT = K3 / GBK;   // 72
    int st = 0;
    for (int kt = 0; kt < KT; kt++) {
        if (kt + 1 < KT) {
            size_t k0n = (size_t)(kt + 1) * GBK;
#pragma unroll
            for (int r = 0; r < 4; r++)
                rA[r] = *reinterpret_cast<const float4*>(Aptr + (size_t)(r * 32) * K3 + k0n);
#pragma unroll
            for (int r = 0; r < 4; r++)
                rB[r] = *reinterpret_cast<const float4*>(Bptr + (k0n + r * 8) * EP3);
        }
        {
            const uint32_t aBase = smA_u + (uint32_t)(st * A_ST) * 4;
            const float* pb = smB + st * B_ST;
#pragma unroll
            for (int ks = 0; ks < 4; ks++) {
                uint32_t a[4][4];
#pragma unroll
                for (int mf = 0; mf < 4; mf++)
                    ldsm4(a[mf], aBase + (uint32_t)(aoff + mf * 16 * APAD + ks * 8) * 4);
                uint32_t b[4][2];
#pragma unroll
                for (int nf = 0; nf < 4; nf++) {
                    b[nf][0] = __float_as_uint(pb[(ks * 8 + bk_f) * BPAD + bn_f + nf * 8]);
                    b[nf][1] = __float_as_uint(pb[(ks * 8 + bk_f + 4) * BPAD + bn_f + nf * 8]);
                }
#pragma unroll
                for (int mf = 0; mf < 4; mf++)
#pragma unroll
                    for (int nf = 0; nf < 4; nf++)
                        mma_tf32(acc[mf][nf], a[mf], b[nf]);
            }
        }
        if (kt + 1 < KT) {
            int ns = st ^ 1;
            float* dA = smA + ns * A_ST;
            float* dB = smB + ns * B_ST;
#pragma unroll
            for (int r = 0; r < 4; r++)
                *reinterpret_cast<float4*>(&dA[(arow + r * 32) * APAD + acol]) = cvt4(rA[r]);
#pragma unroll
            for (int r = 0; r < 4; r++)
                *reinterpret_cast<float4*>(&dB[(brow + r * 8) * BPAD + bcol]) = cvt4(rB[r]);
        }
        __syncthreads();
        st ^= 1;
    }

#pragma unroll
    for (int mf = 0; mf < 4; mf++) {
        int row = bm0 + wm + mf * 16 + (lane >> 2);
#pragma unroll
        for (int nf = 0; nf < 4; nf++) {
            int col = bn0 + wn + nf * 8 + (lane & 3) * 2;
            if (col < CPF) {
                size_t i0 = (size_t)row * NCF + coff + col;
                size_t i1 = i0 + (size_t)8 * NCF;
                *reinterpret_cast<float2*>(g_M + i0) =
                    make_float2(acc[mf][nf][0], acc[mf][nf][1]);
                *reinterpret_cast<float2*>(g_M + i1) =
                    make_float2(acc[mf][nf][2], acc[mf][nf][3]);
            }
        }
    }
}

// ---------------------------------------------------------------------------
// Causal complex cumsum of kf*vf per (batch, bin), times conj(qf). (R2)
// ---------------------------------------------------------------------------
__global__ void scan_kernel() {
    int b = blockIdx.x;
    int mg = blockIdx.y;
    int j = threadIdx.x;   // bin within group (0..7)
    int l = threadIdx.y;   // seq chunk lane (0..31)
    int m = mg * 8 + j;
    bool act = (m < BINS);
    const int CH = SEQ / 32;   // 128
    int sbase = b * SEQ + l * CH;
    int km = 2 * m;

    float sre = 0.f, sim = 0.f;
    if (act) {
        const float* base = g_F + (size_t)sbase * NCF;
        for (int i = 0; i < CH; i++) {
            const float* row = base + (size_t)i * NCF;
            float2 kf = *reinterpret_cast<const float2*>(row + km);
            float2 vf = *reinterpret_cast<const float2*>(row + CPF + km);
            sre += kf.x * vf.x - kf.y * vf.y;
            sim += kf.x * vf.y + kf.y * vf.x;
        }
    }
    __shared__ float pr[8][33], pi[8][33];
    pr[j][l] = sre;
    pi[j][l] = sim;
    __syncthreads();
    if (l == 0) {
        float ar = 0.f, ai = 0.f;
        for (int q = 0; q < 32; q++) {
            float tr_ = pr[j][q], ti = pi[j][q];
            pr[j][q] = ar;
            pi[j][q] = ai;
            ar += tr_;
            ai += ti;
        }
    }
    __syncthreads();
    if (act) {
        float ar = pr[j][l], ai = pi[j][l];
        for (int i = 0; i < CH; i++) {
            int t = sbase + i;
            const float* row = g_F + (size_t)t * NCF;
            float2 kf = *reinterpret_cast<const float2*>(row + km);
            float2 vf = *reinterpret_cast<const float2*>(row + CPF + km);
            float2 qf = *reinterpret_cast<const float2*>(row + 2 * CPF + km);
            ar += kf.x * vf.x - kf.y * vf.y;
            ai += kf.x * vf.y + kf.y * vf.x;
            float outr = ar * qf.x + ai * qf.y;
            float outi = ai * qf.x - ar * qf.y;
            *reinterpret_cast<float2*>(g_OutF + (size_t)t * KPAD + km) =
                make_float2(outr, outi);
        }
    }
}

// ---------------------------------------------------------------------------
// Launch
// ---------------------------------------------------------------------------
extern "C" void kernel_launch(void* const* d_in, const int* in_sizes, int n_in,
                              void* d_out, int out_size) {
    const float* x    = (const float*)d_in[0];
    const float* Wk   = (const float*)d_in[1];
    const float* Wv   = (const float*)d_in[2];
    const float* Wq   = (const float*)d_in[3];
    const float* gain = (const float*)d_in[4];
    float* out = (float*)d_out;

    float *pM, *pF, *pO, *pG;
    cudaGetSymbolAddress((void**)&pM, g_M);
    cudaGetSymbolAddress((void**)&pF, g_F);
    cudaGetSymbolAddress((void**)&pO, g_OutF);
    cudaGetSymbolAddress((void**)&pG, g_G);

    cudaFuncSetAttribute(gemm_tf32, cudaFuncAttributeMaxDynamicSharedMemorySize,
                         GSMEM_BYTES);
    cudaFuncSetAttribute(gemm_pre, cudaFuncAttributeMaxDynamicSharedMemorySize,
                         GSMEM_BYTES);

    transpose_w<<<dim3(DD / 32, DD / 32, 3), dim3(32, 8)>>>(Wk, Wv, Wq);
    fill_E3<<<(K3 * EP3 + 255) / 256, 256>>>();
    fill_G<<<(KPAD * DD + 255) / 256, 256>>>();
    zero_pad_outf<<<(NTOK * (KPAD - CPF) + 255) / 256, 256>>>();

    // Precompute M = W^T E per projection (3xTF32 in one K=2304 pass)
    gemm_pre<<<dim3(EP3 / GBN, DD / GBM, 3), 256, GSMEM_BYTES>>>();

    // Forward: F = x @ M  (tf32 tensor cores, padded N; M pad cols are zero)
    {
        dim3 grid(NCF / GBN, NTOK / GBM, 1);
        gemm_tf32<<<grid, 256, GSMEM_BYTES>>>(NTOK, NCF, DD, x, x, x, DD,
                                              pM, NCF, pF, NCF,
                                              0, 0, nullptr, nullptr);
    }
    // Causal binding scan
    {
        dim3 grid(BATCH, (BINS + 7) / 8, 1);
        scan_kernel<<<grid, dim3(8, 32, 1)>>>();
    }
    // Inverse: out = x + gain * (OutF @ G)  (tf32, padded K)
    {
        dim3 grid(DD / GBN, NTOK / GBM, 1);
        gemm_tf32<<<grid, 256, GSMEM_BYTES>>>(NTOK, DD, KPAD, pO, pO, pO, KPAD,
                                              pG, DD, out, DD,
                                              0, 1, x, gain);
    }
}